// round 15
// baseline (speedup 1.0000x reference)
#include <cuda_runtime.h>
#include <cuda_bf16.h>
#include <math.h>

// ---------------------------------------------------------------------------
// Model_24730421690434  (R14)
//   B=512, T=32, Z=128, K=256, H=512, 4H=2048, Y=4, M=33
// R14: R13 pipeline + (a) next-step prologue issued right after the grid
//      barrier (fill hidden behind Phase C) on the UNCHANGED R13 pipeline,
//      (b) norm+attention precompute folded into recur's idle t=0 slot
//      (norm_attn kernel deleted).
// ---------------------------------------------------------------------------

#define NB 128
#define NT 512

#define BD 512
#define TD 32
#define ZD 128
#define KD 256
#define HD 512
#define YD 4
#define MD 33
#define G4 2048
#define NCHP 51     // chunk space: 0..16 key_r, 17..48 h, 49..50 zero pad
#define NGRP 17     // 17 groups x 3 chunks (last group: only 1 real chunk)
#define ZP 129
#define CHW 3072    // words/staged chunk: A[0,1024) | Bhi[1024,2048) | Blo[2048,3072)
#define SMEM_RECUR (12 * CHW * 4)   // 4 buffers x 3 chunks = 144 KB

// ------------------------------- device state ------------------------------
__device__ __align__(256) unsigned d_BfH[256 * NCHP * 64];
__device__ __align__(256) unsigned d_BfL[256 * NCHP * 64];
__device__ __align__(256) unsigned d_WKfH[32 * 32 * 64];
__device__ __align__(256) unsigned d_WKfL[32 * 32 * 64];
__device__ __align__(256) unsigned d_WEfH[16 * 64 * 64];
__device__ __align__(256) unsigned d_WEfL[16 * 64 * 64];
__device__ __align__(256) unsigned d_AfH[2][32 * NCHP * 128];
__device__ __align__(256) unsigned d_AfL[2][32 * NCHP * 128];

__device__ __align__(256) float d_biasg[G4];
__device__ __align__(256) float d_zbuf[BD * TD * ZD];
__device__ __align__(256) float d_h[BD * HD];
__device__ __align__(256) float d_Mk[(size_t)BD * MD * KD];
__device__ __align__(256) float d_wk[(size_t)BD * MD * MD];
__device__ __align__(256) float d_ck[(size_t)BD * MD * MD];
__device__ unsigned g_cnt1[8 * 32];
__device__ unsigned g_cnt2;
__device__ unsigned g_gen;
__device__ unsigned g_kr;          // key_r producer arrivals (reset in prep)

// reordered chunk index: h chunks (17..48) first, then key_r (0..16), pads
__device__ __forceinline__ int ordc(int i) {
    return (i < 32) ? (17 + i) : ((i < 49) ? (i - 32) : i);
}

__device__ __forceinline__ float tanhap(float x) {
    float y; asm("tanh.approx.f32 %0, %1;" : "=f"(y) : "f"(x)); return y;
}
__device__ __forceinline__ float sigm(float x) {
    return fmaf(tanhap(x * 0.5f), 0.5f, 0.5f);
}

__device__ __forceinline__ void gridBarrier() {
    __syncthreads();
    if (threadIdx.x == 0) {
        const int grp = (blockIdx.x & 7) * 32;
        unsigned gen = *(volatile unsigned*)&g_gen;
        __threadfence();
        if (atomicAdd(&g_cnt1[grp], 1u) == 15u) {
            g_cnt1[grp] = 0u;
            __threadfence();
            if (atomicAdd(&g_cnt2, 1u) == 7u) {
                g_cnt2 = 0u;
                __threadfence();
                atomicAdd(&g_gen, 1u);
            }
        }
        while (*(volatile unsigned*)&g_gen == gen) { __nanosleep(32); }
        __threadfence();
    }
    __syncthreads();
}

__device__ __forceinline__ void cpasync16(void* dst, const void* src) {
    unsigned saddr = (unsigned)__cvta_generic_to_shared(dst);
    asm volatile("cp.async.cg.shared.global [%0], [%1], 16;\n" ::"r"(saddr), "l"(src));
}
#define CPCOMMIT() asm volatile("cp.async.commit_group;\n" ::)
#define CPWAIT(n)  asm volatile("cp.async.wait_group %0;\n" ::"n"(n))

__device__ __forceinline__ void mma16816(float* d, const unsigned* a, const unsigned* b) {
    asm volatile(
        "mma.sync.aligned.m16n8k16.row.col.f32.bf16.bf16.f32 "
        "{%0,%1,%2,%3},{%4,%5,%6,%7},{%8,%9},{%0,%1,%2,%3};"
        : "+f"(d[0]), "+f"(d[1]), "+f"(d[2]), "+f"(d[3])
        : "r"(a[0]), "r"(a[1]), "r"(a[2]), "r"(a[3]), "r"(b[0]), "r"(b[1]));
}

__device__ __forceinline__ unsigned packbf2(float v0, float v1) {
    unsigned short u0 = __bfloat16_as_ushort(__float2bfloat16_rn(v0));
    unsigned short u1 = __bfloat16_as_ushort(__float2bfloat16_rn(v1));
    return (unsigned)u1 << 16 | u0;
}
__device__ __forceinline__ void splitbf2(float v0, float v1, unsigned& hi, unsigned& lo) {
    __nv_bfloat16 h0 = __float2bfloat16_rn(v0);
    __nv_bfloat16 h1 = __float2bfloat16_rn(v1);
    hi = (unsigned)__bfloat16_as_ushort(h1) << 16 | __bfloat16_as_ushort(h0);
    lo = packbf2(v0 - __bfloat162float(h0), v1 - __bfloat162float(h1));
}

// ------------------------------- prep kernel -------------------------------
__device__ __forceinline__ float fetchW(const float* W_ih, const float* W_hh,
                                        int n, int k) {
    if (k < 257) return W_ih[n * 257 + k];
    if (k >= 272 && k < 784) return W_hh[n * HD + (k - 272)];
    return 0.f;
}

__global__ void __launch_bounds__(256) prep_kernel(
    const float* __restrict__ W_ih, const float* __restrict__ W_hh,
    const float* __restrict__ b_ih, const float* __restrict__ b_hh,
    const float* __restrict__ W_key, const float* __restrict__ W_enc)
{
    const int stride = gridDim.x * blockDim.x;
    const int gtid = blockIdx.x * blockDim.x + threadIdx.x;
    if (gtid == 0) g_kr = 0u;

    for (int idx = gtid; idx < 256 * NCHP * 64; idx += stride) {
        int n8 = idx / (NCHP * 64);
        int rem = idx - n8 * (NCHP * 64);
        int c = rem >> 6;
        int lw = rem & 63;
        int lane = lw >> 1, w = lw & 1;
        int lr = lane >> 2, lc = lane & 3;
        int np = n8 * 8 + lr;
        int g = np & 3, j = np >> 2;
        int orig = g * 512 + j;
        int k = c * 16 + w * 8 + lc * 2;
        float v0 = (k < 784) ? fetchW(W_ih, W_hh, orig, k) : 0.f;
        float v1 = (k + 1 < 784) ? fetchW(W_ih, W_hh, orig, k + 1) : 0.f;
        splitbf2(v0, v1, d_BfH[idx], d_BfL[idx]);
    }
    for (int idx = gtid; idx < 32 * 32 * 64; idx += stride) {
        int n8 = idx / (32 * 64);
        int rem = idx - n8 * (32 * 64);
        int c = rem >> 6;
        int lw = rem & 63;
        int lane = lw >> 1, w = lw & 1;
        int lr = lane >> 2, lc = lane & 3;
        int n = n8 * 8 + lr;
        int k = c * 16 + w * 8 + lc * 2;
        splitbf2(W_key[n * HD + k], W_key[n * HD + k + 1],
                 d_WKfH[idx], d_WKfL[idx]);
    }
    for (int idx = gtid; idx < 16 * 64 * 64; idx += stride) {
        int n8 = idx / (64 * 64);
        int rem = idx - n8 * (64 * 64);
        int c = rem >> 6;
        int lw = rem & 63;
        int lane = lw >> 1, w = lw & 1;
        int lr = lane >> 2, lc = lane & 3;
        int n = n8 * 8 + lr;
        int k = c * 16 + w * 8 + lc * 2;
        splitbf2(W_enc[k * ZD + n], W_enc[(k + 1) * ZD + n],
                 d_WEfH[idx], d_WEfL[idx]);
    }
    for (int np = gtid; np < G4; np += stride) {
        int orig = (np & 3) * 512 + (np >> 2);
        d_biasg[np] = b_ih[orig] + b_hh[orig];
    }
    // zero ONLY the pad chunks (49,50)
    for (int idx = gtid; idx < 32 * 2 * 128; idx += stride) {
        int m16 = idx >> 8;
        int r = idx & 255;
        int ch = 49 + (r >> 7);
        int wq = r & 127;
        size_t off = ((size_t)(m16 * NCHP + ch)) * 128 + wq;
        d_AfH[0][off] = 0u; d_AfL[0][off] = 0u;
        d_AfH[1][off] = 0u; d_AfL[1][off] = 0u;
    }
}

// ------------------- encoder GEMM on tensor cores --------------------------
__global__ void __launch_bounds__(256) enc_gemm2(const float* __restrict__ X)
{
    const int tid = threadIdx.x;
    const int lane = tid & 31, wid = tid >> 5;
    const int lr = lane >> 2, lc = lane & 3;
    const int m16 = blockIdx.x * 8 + wid;

    const float* xr0 = X + (size_t)(m16 * 16 + lr) * 1024;
    const float* xr1 = xr0 + 8 * 1024;

    float acc[16][4];
#pragma unroll
    for (int n8 = 0; n8 < 16; n8++)
#pragma unroll
        for (int r = 0; r < 4; r++) acc[n8][r] = 0.f;

#pragma unroll 1
    for (int c = 0; c < 64; c++) {
        int k = c * 16 + lc * 2;
        float2 x00 = *(const float2*)(xr0 + k);
        float2 x10 = *(const float2*)(xr1 + k);
        float2 x01 = *(const float2*)(xr0 + k + 8);
        float2 x11 = *(const float2*)(xr1 + k + 8);
        unsigned aH[4], aL[4];
        splitbf2(x00.x, x00.y, aH[0], aL[0]);
        splitbf2(x10.x, x10.y, aH[1], aL[1]);
        splitbf2(x01.x, x01.y, aH[2], aL[2]);
        splitbf2(x11.x, x11.y, aH[3], aL[3]);
#pragma unroll
        for (int n8 = 0; n8 < 16; n8++) {
            const unsigned* pH = d_WEfH + (size_t)(n8 * 64 + c) * 64 + lane * 2;
            const unsigned* pL = d_WEfL + (size_t)(n8 * 64 + c) * 64 + lane * 2;
            unsigned bH[2], bL[2];
            *(uint2*)bH = *(const uint2*)pH;
            *(uint2*)bL = *(const uint2*)pL;
            mma16816(acc[n8], aH, bH);
            mma16816(acc[n8], aH, bL);
            mma16816(acc[n8], aL, bH);
        }
    }
    int row0 = m16 * 16 + lr;
#pragma unroll
    for (int n8 = 0; n8 < 16; n8++) {
        int col = n8 * 8 + lc * 2;
        *(float2*)(d_zbuf + (size_t)row0 * ZD + col)       = make_float2(acc[n8][0], acc[n8][1]);
        *(float2*)(d_zbuf + (size_t)(row0 + 8) * ZD + col) = make_float2(acc[n8][2], acc[n8][3]);
    }
}

// ------------------------- persistent recurrence ---------------------------
__global__ void __launch_bounds__(NT) recur(
    const float* __restrict__ b_key, const float* __restrict__ W_g,
    const float* __restrict__ b_g,   const float* __restrict__ W_y,
    const float* __restrict__ b_y,
    const float* __restrict__ gamma, const float* __restrict__ beta,
    const float* __restrict__ cgain, const float* __restrict__ cbias,
    void* outp, int out_size)
{
    extern __shared__ unsigned sS[];   // 4 buffers x 3 chunks x 3072 words

    const int tid = threadIdx.x;
    const int bx = blockIdx.x;
    const int lane = tid & 31, wid = tid >> 5;
    const int lr = lane >> 2, lc = lane & 3;

    const int mblk = bx >> 4, nblk = bx & 15;
    const int wmm = wid & 3;
    const int wn  = wid >> 2;
    const int m16g = mblk * 4 + wmm;

    const int t8      = tid & 255;
    const int a_plane = t8 >> 7;
    const int a_m16A  = mblk * 4 + ((t8 >> 5) & 3);
    const int a_widx  = (t8 & 31) * 4;
    const int a_soff  = a_plane * 512 + ((t8 >> 5) & 3) * 128 + a_widx;

    const int b_plane = tid >> 8;
    const int b_n8l   = (tid >> 4) & 15;
    const int b_w4    = (tid & 15) * 4;
    const int b_soff  = 1024 + b_plane * 1024 + b_n8l * 64 + b_w4;
    const unsigned* bSrc = (b_plane ? d_BfL : d_BfH) +
                           (size_t)(nblk * 16 + b_n8l) * (NCHP * 64) + b_w4;

    float4 bias4[4];
#pragma unroll
    for (int jj = 0; jj < 4; jj++) {
        int n8g = nblk * 16 + wn * 4 + jj;
        int jq = n8g * 2 + (lc >> 1);
        bias4[jj] = *(const float4*)(d_biasg + jq * 4);
    }

    const bool odd = (lc & 1);
    float cc4[4] = {0.f, 0.f, 0.f, 0.f};

    for (int t = 0; t < MD; t++) {
        const int cur = t & 1, pn = (t + 1) & 1;
        // ============ Phase A: gate GEMM + fused cell =======================
        {
            float acc[4][4];
#pragma unroll
            for (int j = 0; j < 4; j++)
#pragma unroll
                for (int r = 0; r < 4; r++) acc[j][r] = 0.f;

            if (t == 0) {
                // ---- t=0: GEMM is all-zero; use the slot for norm+attn -----
                float* zs = (float*)sS;            // TD*ZP floats
                float* S  = (float*)sS + TD * ZP;  // TD*TD floats
                const float cg = cgain[0], cb = cbias[0];
#pragma unroll 1
                for (int bi = 0; bi < 4; bi++) {
                    int b = bx * 4 + bi;
                    __syncthreads();
                    if (tid < 128) {
                        float v[TD];
                        float s = 0.f;
#pragma unroll
                        for (int tt = 0; tt < TD; tt++) {
                            v[tt] = d_zbuf[((size_t)(b * TD) + tt) * ZD + tid];
                            s += v[tt];
                        }
                        float mu = s * (1.f / TD);
                        float q = 0.f;
#pragma unroll
                        for (int tt = 0; tt < TD; tt++) { float d = v[tt] - mu; q += d * d; }
                        float inv = rsqrtf(q * (1.f / TD) + 1e-8f);
                        float ga = gamma[tid], be = beta[tid];
#pragma unroll
                        for (int tt = 0; tt < TD; tt++)
                            zs[tt * ZP + tid] = (v[tt] - mu) * inv * ga + be;
                    }
                    __syncthreads();
                    for (int p = tid; p < TD * TD; p += NT) {
                        int tt = p >> 5, m = p & 31;
                        if (m < tt) {
                            const float* zt = zs + tt * ZP;
                            const float* zm = zs + m * ZP;
                            float s = 0.f;
#pragma unroll 8
                            for (int i = 0; i < ZD; i++) s += zt[i] * zm[i];
                            S[p] = s;
                        }
                    }
                    __syncthreads();
#pragma unroll
                    for (int it = 0; it < 2; it++) {
                        int tt = 1 + wid + it * 16;
                        if (tt <= 31) {
                            float sv = (lane < tt) ? S[tt * TD + lane] : -3.4e38f;
                            float mx = sv;
#pragma unroll
                            for (int o = 16; o; o >>= 1)
                                mx = fmaxf(mx, __shfl_xor_sync(0xffffffffu, mx, o));
                            float e = (lane < tt) ? __expf(sv - mx) : 0.f;
                            float sum = e;
#pragma unroll
                            for (int o = 16; o; o >>= 1)
                                sum += __shfl_xor_sync(0xffffffffu, sum, o);
                            float inv = __fdividef(1.f, sum);
                            if (lane < tt) {
                                d_wk[((size_t)b * MD + tt) * MD + lane] = e * inv;
                                d_ck[((size_t)b * MD + tt) * MD + lane] = sigm(sv * cg + cb);
                            }
                        }
                    }
                }
                __syncthreads();
            } else {
                const unsigned* aSrc = (a_plane ? d_AfL[cur] : d_AfH[cur]) +
                                       (size_t)a_m16A * (NCHP * 128) + a_widx;
                // NOTE: prologue groups 0..2 already in flight (issued after
                // the previous step's grid barrier, before Phase C)
                int bufIdx = 0;
#pragma unroll 1
                for (int g = 0; g < NGRP; g++) {
                    int sg = g + 3;
                    CPWAIT(2);
                    __syncthreads();
                    if (sg == 10) {   // about to stage first key_r chunk
                        if (tid == 0) {
                            unsigned tgt = 128u * (unsigned)t;
                            while (*(volatile unsigned*)&g_kr < tgt) { __nanosleep(32); }
                            __threadfence();
                        }
                        __syncthreads();
                    }
                    if (sg < NGRP) {
                        int nbuf = bufIdx + 3; if (nbuf >= 4) nbuf -= 4;
                        int nsc = (sg == NGRP - 1) ? 1 : 3;
#pragma unroll
                        for (int ccq = 0; ccq < 3; ccq++) {
                            if (ccq < nsc) {
                                int ch = ordc(sg * 3 + ccq);
                                unsigned* dst = sS + (size_t)(nbuf * 3 + ccq) * CHW;
                                if (tid < 256) cpasync16(dst + a_soff, aSrc + ch * 128);
                                cpasync16(dst + b_soff, bSrc + ch * 64);
                            }
                        }
                    }
                    CPCOMMIT();
                    const unsigned* gb = sS + (size_t)bufIdx * 3 * CHW;
                    int ncc = (g == NGRP - 1) ? 1 : 3;
#pragma unroll
                    for (int ccq = 0; ccq < 3; ccq++) {
                        if (ccq >= ncc) break;
                        const unsigned* base = gb + ccq * CHW;
                        unsigned aH[4], aL[4];
                        *(uint4*)aH = *(const uint4*)(base + wmm * 128 + lane * 4);
                        *(uint4*)aL = *(const uint4*)(base + 512 + wmm * 128 + lane * 4);
                        unsigned bH[4][2], bL[4][2];
#pragma unroll
                        for (int jj = 0; jj < 4; jj++) {
                            *(uint2*)bH[jj] = *(const uint2*)(base + 1024 + (wn * 4 + jj) * 64 + lane * 2);
                            *(uint2*)bL[jj] = *(const uint2*)(base + 2048 + (wn * 4 + jj) * 64 + lane * 2);
                        }
#pragma unroll
                        for (int jj = 0; jj < 4; jj++) mma16816(acc[jj], aH, bH[jj]);
#pragma unroll
                        for (int jj = 0; jj < 4; jj++) mma16816(acc[jj], aH, bL[jj]);
#pragma unroll
                        for (int jj = 0; jj < 4; jj++) mma16816(acc[jj], aL, bH[jj]);
                    }
                    bufIdx++; if (bufIdx == 4) bufIdx = 0;
                }
            }

            // ---- fused epilogue: gates + cell update + h frag stores ----
            unsigned* hOutH = d_AfH[pn];
            unsigned* hOutL = d_AfL[pn];
#pragma unroll
            for (int jj = 0; jj < 4; jj++) {
                float a0 = acc[jj][0], a1 = acc[jj][1];
                float a2 = acc[jj][2], a3 = acc[jj][3];
                float p0 = __shfl_xor_sync(0xffffffffu, odd ? a0 : a2, 1);
                float p1 = __shfl_xor_sync(0xffffffffu, odd ? a1 : a3, 1);
                float4 bb4 = bias4[jj];
                float gi, gf, gg, go;
                if (!odd) { gi = a0 + bb4.x; gf = a1 + bb4.y; gg = p0 + bb4.z; go = p1 + bb4.w; }
                else      { gi = p0 + bb4.x; gf = p1 + bb4.y; gg = a2 + bb4.z; go = a3 + bb4.w; }
                float cn = sigm(gf) * cc4[jj] + sigm(gi) * tanhap(gg);
                cc4[jj] = cn;
                float hv = sigm(go) * tanhap(cn);
                int n8g = nblk * 16 + wn * 4 + jj;
                int jq = n8g * 2 + (lc >> 1);
                int row = m16g * 16 + lr + (odd ? 8 : 0);
                d_h[row * HD + jq] = hv;
                __nv_bfloat16 hh = __float2bfloat16_rn(hv);
                __nv_bfloat16 hl = __float2bfloat16_rn(hv - __bfloat162float(hh));
                unsigned uh = (unsigned)__bfloat16_as_ushort(hh);
                unsigned ul = (unsigned)__bfloat16_as_ushort(hl);
                unsigned ph = __shfl_xor_sync(0xffffffffu, uh, 2);
                unsigned pl = __shfl_xor_sync(0xffffffffu, ul, 2);
                if ((lc & 2) == 0) {
                    int kk = jq & 15;
                    int ch = 17 + (jq >> 4);
                    int lane_a = lr * 4 + ((kk & 7) >> 1);
                    int w = (odd ? 1 : 0) + ((kk >> 3) << 1);
                    size_t widx = ((size_t)(m16g * NCHP + ch)) * 128 + lane_a * 4 + w;
                    hOutH[widx] = (ph << 16) | uh;
                    hOutL[widx] = (pl << 16) | ul;
                }
            }
        }
        gridBarrier();  // h, Mk(t-1), (t=0: wk/ck) visible everywhere

        // ---- issue next step's prologue NOW (fill hidden behind Phase C) ---
        if (t < MD - 1) {
            const unsigned* aSrcN = (a_plane ? d_AfL[pn] : d_AfH[pn]) +
                                    (size_t)a_m16A * (NCHP * 128) + a_widx;
#pragma unroll
            for (int p = 0; p < 3; p++) {
#pragma unroll
                for (int ccq = 0; ccq < 3; ccq++) {
                    int ch = ordc(p * 3 + ccq);   // h region only
                    unsigned* dst = sS + (size_t)(p * 3 + ccq) * CHW;
                    if (tid < 256) cpasync16(dst + a_soff, aSrcN + ch * 128);
                    cpasync16(dst + b_soff, bSrc + ch * 64);
                }
                CPCOMMIT();
            }
        }

        // ============ Phase C ==============================================
        if (t < TD) {
            if (bx < 64) {  // key_w = relu(h @ W_key^T + b_key), dual-chain
                const int m16 = (bx >> 3) * 4 + (wid & 3);
                const int n8  = (bx & 7) * 4 + (wid >> 2);
                const unsigned* pAH = d_AfH[pn] + ((size_t)m16 * NCHP + 17) * 128 + lane * 4;
                const unsigned* pAL = d_AfL[pn] + ((size_t)m16 * NCHP + 17) * 128 + lane * 4;
                const unsigned* pWH = d_WKfH + (size_t)n8 * (32 * 64) + lane * 2;
                const unsigned* pWL = d_WKfL + (size_t)n8 * (32 * 64) + lane * 2;
                float ka[4] = {0.f, 0.f, 0.f, 0.f};
                float kb[4] = {0.f, 0.f, 0.f, 0.f};
                unsigned cAH0[4], cAL0[4], cW0H[2], cW0L[2];
                unsigned cAH1[4], cAL1[4], cW1H[2], cW1L[2];
                *(uint4*)cAH0 = *(const uint4*)(pAH);
                *(uint4*)cAL0 = *(const uint4*)(pAL);
                *(uint2*)cW0H = *(const uint2*)(pWH);
                *(uint2*)cW0L = *(const uint2*)(pWL);
                *(uint4*)cAH1 = *(const uint4*)(pAH + 16 * 128);
                *(uint4*)cAL1 = *(const uint4*)(pAL + 16 * 128);
                *(uint2*)cW1H = *(const uint2*)(pWH + 16 * 64);
                *(uint2*)cW1L = *(const uint2*)(pWL + 16 * 64);
#pragma unroll 1
                for (int ch = 0; ch < 16; ch++) {
                    unsigned nAH0[4], nAL0[4], nW0H[2], nW0L[2];
                    unsigned nAH1[4], nAL1[4], nW1H[2], nW1L[2];
                    if (ch < 15) {
                        *(uint4*)nAH0 = *(const uint4*)(pAH + (ch + 1) * 128);
                        *(uint4*)nAL0 = *(const uint4*)(pAL + (ch + 1) * 128);
                        *(uint2*)nW0H = *(const uint2*)(pWH + (ch + 1) * 64);
                        *(uint2*)nW0L = *(const uint2*)(pWL + (ch + 1) * 64);
                        *(uint4*)nAH1 = *(const uint4*)(pAH + (ch + 17) * 128);
                        *(uint4*)nAL1 = *(const uint4*)(pAL + (ch + 17) * 128);
                        *(uint2*)nW1H = *(const uint2*)(pWH + (ch + 17) * 64);
                        *(uint2*)nW1L = *(const uint2*)(pWL + (ch + 17) * 64);
                    }
                    mma16816(ka, cAH0, cW0H);
                    mma16816(kb, cAH1, cW1H);
                    mma16816(ka, cAH0, cW0L);
                    mma16816(kb, cAH1, cW1L);
                    mma16816(ka, cAL0, cW0H);
                    mma16816(kb, cAL1, cW1H);
                    if (ch < 15) {
                        *(uint4*)cAH0 = *(uint4*)nAH0; *(uint4*)cAL0 = *(uint4*)nAL0;
                        *(uint2*)cW0H = *(uint2*)nW0H; *(uint2*)cW0L = *(uint2*)nW0L;
                        *(uint4*)cAH1 = *(uint4*)nAH1; *(uint4*)cAL1 = *(uint4*)nAL1;
                        *(uint2*)cW1H = *(uint2*)nW1H; *(uint2*)cW1L = *(uint2*)nW1L;
                    }
                }
#pragma unroll
                for (int r = 0; r < 4; r++) ka[r] += kb[r];
                int col = n8 * 8 + lc * 2;
                float bk0 = b_key[col], bk1 = b_key[col + 1];
                int row0 = m16 * 16 + lr;
                float2 v0 = {fmaxf(ka[0] + bk0, 0.f), fmaxf(ka[1] + bk1, 0.f)};
                float2 v1 = {fmaxf(ka[2] + bk0, 0.f), fmaxf(ka[3] + bk1, 0.f)};
                *(float2*)(d_Mk + ((size_t)row0 * MD + t) * KD + col) = v0;
                *(float2*)(d_Mk + ((size_t)(row0 + 8) * MD + t) * KD + col) = v1;
            } else {  // gate g + attention read -> key_r fragments (parity pn)
                int bb = (bx - 64) * 8 + (wid & 7);
                const float* hb = d_h + (size_t)bb * HD;
                float s = 0.f;
                for (int l = lane; l < HD; l += 32) s += hb[l] * W_g[l];
#pragma unroll
                for (int o = 16; o; o >>= 1) s += __shfl_xor_sync(0xffffffffu, s, o);
                float gv = sigm(s + b_g[0]);
                const float* wkb = d_wk + ((size_t)bb * MD + t) * MD;
                const float* ckb = d_ck + ((size_t)bb * MD + t) * MD;
                const float* mkb = d_Mk + (size_t)bb * MD * KD;
                int m16 = bb >> 4, r = bb & 15;
                unsigned* oH = d_AfH[pn];
                unsigned* oL = d_AfL[pn];
                for (int dp = lane + ((wid >> 3) << 5); dp < 129; dp += 64) {
                    int d0 = dp * 2;
                    float v0 = 0.f, v1 = 0.f;
                    if (d0 < 256) {
                        int m = 0;
                        for (; m + 4 <= t; m += 4) {
                            float w0 = wkb[m], w1 = wkb[m + 1];
                            float w2 = wkb[m + 2], w3 = wkb[m + 3];
                            float x0 = mkb[(m) * KD + d0],     y0 = mkb[(m) * KD + d0 + 1];
                            float x1 = mkb[(m + 1) * KD + d0], y1 = mkb[(m + 1) * KD + d0 + 1];
                            float x2 = mkb[(m + 2) * KD + d0], y2 = mkb[(m + 2) * KD + d0 + 1];
                            float x3 = mkb[(m + 3) * KD + d0], y3 = mkb[(m + 3) * KD + d0 + 1];
                            v0 += w0 * x0 + w1 * x1 + w2 * x2 + w3 * x3;
                            v1 += w0 * y0 + w1 * y1 + w2 * y2 + w3 * y3;
                        }
                        for (; m < t; m++) {
                            float w = wkb[m];
                            v0 += w * mkb[m * KD + d0];
                            v1 += w * mkb[m * KD + d0 + 1];
                        }
                    } else {
                        for (int m = 0; m < t; m++) v0 += wkb[m] * ckb[m];
                    }
                    v0 *= gv; v1 *= gv;
                    __nv_bfloat16 h0 = __float2bfloat16_rn(v0);
                    __nv_bfloat16 h1 = __float2bfloat16_rn(v1);
                    int ch = d0 >> 4, kk = d0 & 15;
                    int lane_a = (r & 7) * 4 + ((kk & 7) >> 1);
                    int w = (r >> 3) + ((kk >> 3) << 1);
                    size_t widx = ((size_t)(m16 * NCHP + ch)) * 128 + lane_a * 4 + w;
                    oH[widx] = (unsigned)__bfloat16_as_ushort(h1) << 16 |
                               __bfloat16_as_ushort(h0);
                    oL[widx] = packbf2(v0 - __bfloat162float(h0),
                                       v1 - __bfloat162float(h1));
                }
            }
            // producer arrival: key_r (and Mk) for step t complete on this block
            __syncthreads();
            if (tid == 0) { __threadfence(); atomicAdd(&g_kr, 1u); }
        } else {  // t == 32: y_lin + argmax
            if (bx >= 64 && bx < 128 && wid < 8) {
                int bb = (bx - 64) * 8 + wid;
                const float* hb = d_h + (size_t)bb * HD;
                float yv[4];
#pragma unroll
                for (int yi = 0; yi < YD; yi++) {
                    float s = 0.f;
                    for (int l = lane; l < HD; l += 32) s += hb[l] * W_y[yi * HD + l];
#pragma unroll
                    for (int o = 16; o; o >>= 1) s += __shfl_xor_sync(0xffffffffu, s, o);
                    yv[yi] = s + b_y[yi];
                }
                if (lane == 0) {
                    int am = 0; float bst = yv[0];
#pragma unroll
                    for (int yi = 1; yi < YD; yi++)
                        if (yv[yi] > bst) { bst = yv[yi]; am = yi; }
                    if (out_size >= BD * YD) {
                        float* of = (float*)outp;
                        of[bb * 4 + 0] = yv[0];
                        of[bb * 4 + 1] = yv[1];
                        of[bb * 4 + 2] = yv[2];
                        of[bb * 4 + 3] = yv[3];
                        if (out_size >= BD * YD + BD) of[BD * YD + bb] = (float)am;
                    } else {
                        ((int*)outp)[bb] = am;
                    }
                }
            }
        }
    }
}

// ------------------------------- launcher ----------------------------------
extern "C" void kernel_launch(void* const* d_in, const int* in_sizes, int n_in,
                              void* d_out, int out_size)
{
    const float* x_seq  = (const float*)d_in[0];
    const float* W_enc  = (const float*)d_in[1];
    const float* gamma  = (const float*)d_in[2];
    const float* beta   = (const float*)d_in[3];
    const float* W_ih   = (const float*)d_in[4];
    const float* W_hh   = (const float*)d_in[5];
    const float* b_ih   = (const float*)d_in[6];
    const float* b_hh   = (const float*)d_in[7];
    const float* W_key  = (const float*)d_in[8];
    const float* b_key  = (const float*)d_in[9];
    const float* W_g    = (const float*)d_in[10];
    const float* b_g    = (const float*)d_in[11];
    const float* cgain  = (const float*)d_in[12];
    const float* cbias  = (const float*)d_in[13];
    const float* W_y    = (const float*)d_in[14];
    const float* b_y    = (const float*)d_in[15];

    cudaFuncSetAttribute(recur, cudaFuncAttributeMaxDynamicSharedMemorySize,
                         SMEM_RECUR);

    prep_kernel<<<1024, 256>>>(W_ih, W_hh, b_ih, b_hh, W_key, W_enc);
    enc_gemm2<<<128, 256>>>(x_seq);
    recur<<<NB, NT, SMEM_RECUR>>>(b_key, W_g, b_g, W_y, b_y,
                                  gamma, beta, cgain, cbias, d_out, out_size);
}

// round 16
// speedup vs baseline: 1.0116x; 1.0116x over previous
#include <cuda_runtime.h>
#include <cuda_bf16.h>
#include <math.h>

// ---------------------------------------------------------------------------
// Model_24730421690434  (R15)
//   B=512, T=32, Z=128, K=256, H=512, 4H=2048, Y=4, M=33
// R15: exact R13 pipeline (prologue at top of Phase A, 3-chunk groups,
//      4 buffers, CPWAIT(2), pad-free last group) + SINGLE change:
//      norm+attention precompute folded into recur's idle t=0 slot
//      (norm_attn kernel deleted).
// ---------------------------------------------------------------------------

#define NB 128
#define NT 512

#define BD 512
#define TD 32
#define ZD 128
#define KD 256
#define HD 512
#define YD 4
#define MD 33
#define G4 2048
#define NCHP 51     // chunk space: 0..16 key_r, 17..48 h, 49..50 zero pad
#define NGRP 17     // 17 groups x 3 chunks (last group: only 1 real chunk)
#define ZP 129
#define CHW 3072    // words/staged chunk: A[0,1024) | Bhi[1024,2048) | Blo[2048,3072)
#define SMEM_RECUR (12 * CHW * 4)   // 4 buffers x 3 chunks = 144 KB

// ------------------------------- device state ------------------------------
__device__ __align__(256) unsigned d_BfH[256 * NCHP * 64];
__device__ __align__(256) unsigned d_BfL[256 * NCHP * 64];
__device__ __align__(256) unsigned d_WKfH[32 * 32 * 64];
__device__ __align__(256) unsigned d_WKfL[32 * 32 * 64];
__device__ __align__(256) unsigned d_WEfH[16 * 64 * 64];
__device__ __align__(256) unsigned d_WEfL[16 * 64 * 64];
__device__ __align__(256) unsigned d_AfH[2][32 * NCHP * 128];
__device__ __align__(256) unsigned d_AfL[2][32 * NCHP * 128];

__device__ __align__(256) float d_biasg[G4];
__device__ __align__(256) float d_zbuf[BD * TD * ZD];
__device__ __align__(256) float d_h[BD * HD];
__device__ __align__(256) float d_Mk[(size_t)BD * MD * KD];
__device__ __align__(256) float d_wk[(size_t)BD * MD * MD];
__device__ __align__(256) float d_ck[(size_t)BD * MD * MD];
__device__ unsigned g_cnt1[8 * 32];
__device__ unsigned g_cnt2;
__device__ unsigned g_gen;
__device__ unsigned g_kr;          // key_r producer arrivals (reset in prep)

// reordered chunk index: h chunks (17..48) first, then key_r (0..16), pads
__device__ __forceinline__ int ordc(int i) {
    return (i < 32) ? (17 + i) : ((i < 49) ? (i - 32) : i);
}

__device__ __forceinline__ float tanhap(float x) {
    float y; asm("tanh.approx.f32 %0, %1;" : "=f"(y) : "f"(x)); return y;
}
__device__ __forceinline__ float sigm(float x) {
    return fmaf(tanhap(x * 0.5f), 0.5f, 0.5f);
}

__device__ __forceinline__ void gridBarrier() {
    __syncthreads();
    if (threadIdx.x == 0) {
        const int grp = (blockIdx.x & 7) * 32;
        unsigned gen = *(volatile unsigned*)&g_gen;
        __threadfence();
        if (atomicAdd(&g_cnt1[grp], 1u) == 15u) {
            g_cnt1[grp] = 0u;
            __threadfence();
            if (atomicAdd(&g_cnt2, 1u) == 7u) {
                g_cnt2 = 0u;
                __threadfence();
                atomicAdd(&g_gen, 1u);
            }
        }
        while (*(volatile unsigned*)&g_gen == gen) { __nanosleep(32); }
        __threadfence();
    }
    __syncthreads();
}

__device__ __forceinline__ void cpasync16(void* dst, const void* src) {
    unsigned saddr = (unsigned)__cvta_generic_to_shared(dst);
    asm volatile("cp.async.cg.shared.global [%0], [%1], 16;\n" ::"r"(saddr), "l"(src));
}
#define CPCOMMIT() asm volatile("cp.async.commit_group;\n" ::)
#define CPWAIT(n)  asm volatile("cp.async.wait_group %0;\n" ::"n"(n))

__device__ __forceinline__ void mma16816(float* d, const unsigned* a, const unsigned* b) {
    asm volatile(
        "mma.sync.aligned.m16n8k16.row.col.f32.bf16.bf16.f32 "
        "{%0,%1,%2,%3},{%4,%5,%6,%7},{%8,%9},{%0,%1,%2,%3};"
        : "+f"(d[0]), "+f"(d[1]), "+f"(d[2]), "+f"(d[3])
        : "r"(a[0]), "r"(a[1]), "r"(a[2]), "r"(a[3]), "r"(b[0]), "r"(b[1]));
}

__device__ __forceinline__ unsigned packbf2(float v0, float v1) {
    unsigned short u0 = __bfloat16_as_ushort(__float2bfloat16_rn(v0));
    unsigned short u1 = __bfloat16_as_ushort(__float2bfloat16_rn(v1));
    return (unsigned)u1 << 16 | u0;
}
__device__ __forceinline__ void splitbf2(float v0, float v1, unsigned& hi, unsigned& lo) {
    __nv_bfloat16 h0 = __float2bfloat16_rn(v0);
    __nv_bfloat16 h1 = __float2bfloat16_rn(v1);
    hi = (unsigned)__bfloat16_as_ushort(h1) << 16 | __bfloat16_as_ushort(h0);
    lo = packbf2(v0 - __bfloat162float(h0), v1 - __bfloat162float(h1));
}

// ------------------------------- prep kernel -------------------------------
__device__ __forceinline__ float fetchW(const float* W_ih, const float* W_hh,
                                        int n, int k) {
    if (k < 257) return W_ih[n * 257 + k];
    if (k >= 272 && k < 784) return W_hh[n * HD + (k - 272)];
    return 0.f;
}

__global__ void __launch_bounds__(256) prep_kernel(
    const float* __restrict__ W_ih, const float* __restrict__ W_hh,
    const float* __restrict__ b_ih, const float* __restrict__ b_hh,
    const float* __restrict__ W_key, const float* __restrict__ W_enc)
{
    const int stride = gridDim.x * blockDim.x;
    const int gtid = blockIdx.x * blockDim.x + threadIdx.x;
    if (gtid == 0) g_kr = 0u;

    for (int idx = gtid; idx < 256 * NCHP * 64; idx += stride) {
        int n8 = idx / (NCHP * 64);
        int rem = idx - n8 * (NCHP * 64);
        int c = rem >> 6;
        int lw = rem & 63;
        int lane = lw >> 1, w = lw & 1;
        int lr = lane >> 2, lc = lane & 3;
        int np = n8 * 8 + lr;
        int g = np & 3, j = np >> 2;
        int orig = g * 512 + j;
        int k = c * 16 + w * 8 + lc * 2;
        float v0 = (k < 784) ? fetchW(W_ih, W_hh, orig, k) : 0.f;
        float v1 = (k + 1 < 784) ? fetchW(W_ih, W_hh, orig, k + 1) : 0.f;
        splitbf2(v0, v1, d_BfH[idx], d_BfL[idx]);
    }
    for (int idx = gtid; idx < 32 * 32 * 64; idx += stride) {
        int n8 = idx / (32 * 64);
        int rem = idx - n8 * (32 * 64);
        int c = rem >> 6;
        int lw = rem & 63;
        int lane = lw >> 1, w = lw & 1;
        int lr = lane >> 2, lc = lane & 3;
        int n = n8 * 8 + lr;
        int k = c * 16 + w * 8 + lc * 2;
        splitbf2(W_key[n * HD + k], W_key[n * HD + k + 1],
                 d_WKfH[idx], d_WKfL[idx]);
    }
    for (int idx = gtid; idx < 16 * 64 * 64; idx += stride) {
        int n8 = idx / (64 * 64);
        int rem = idx - n8 * (64 * 64);
        int c = rem >> 6;
        int lw = rem & 63;
        int lane = lw >> 1, w = lw & 1;
        int lr = lane >> 2, lc = lane & 3;
        int n = n8 * 8 + lr;
        int k = c * 16 + w * 8 + lc * 2;
        splitbf2(W_enc[k * ZD + n], W_enc[(k + 1) * ZD + n],
                 d_WEfH[idx], d_WEfL[idx]);
    }
    for (int np = gtid; np < G4; np += stride) {
        int orig = (np & 3) * 512 + (np >> 2);
        d_biasg[np] = b_ih[orig] + b_hh[orig];
    }
    // zero ONLY the pad chunks (49,50)
    for (int idx = gtid; idx < 32 * 2 * 128; idx += stride) {
        int m16 = idx >> 8;
        int r = idx & 255;
        int ch = 49 + (r >> 7);
        int wq = r & 127;
        size_t off = ((size_t)(m16 * NCHP + ch)) * 128 + wq;
        d_AfH[0][off] = 0u; d_AfL[0][off] = 0u;
        d_AfH[1][off] = 0u; d_AfL[1][off] = 0u;
    }
}

// ------------------- encoder GEMM on tensor cores --------------------------
__global__ void __launch_bounds__(256) enc_gemm2(const float* __restrict__ X)
{
    const int tid = threadIdx.x;
    const int lane = tid & 31, wid = tid >> 5;
    const int lr = lane >> 2, lc = lane & 3;
    const int m16 = blockIdx.x * 8 + wid;

    const float* xr0 = X + (size_t)(m16 * 16 + lr) * 1024;
    const float* xr1 = xr0 + 8 * 1024;

    float acc[16][4];
#pragma unroll
    for (int n8 = 0; n8 < 16; n8++)
#pragma unroll
        for (int r = 0; r < 4; r++) acc[n8][r] = 0.f;

#pragma unroll 1
    for (int c = 0; c < 64; c++) {
        int k = c * 16 + lc * 2;
        float2 x00 = *(const float2*)(xr0 + k);
        float2 x10 = *(const float2*)(xr1 + k);
        float2 x01 = *(const float2*)(xr0 + k + 8);
        float2 x11 = *(const float2*)(xr1 + k + 8);
        unsigned aH[4], aL[4];
        splitbf2(x00.x, x00.y, aH[0], aL[0]);
        splitbf2(x10.x, x10.y, aH[1], aL[1]);
        splitbf2(x01.x, x01.y, aH[2], aL[2]);
        splitbf2(x11.x, x11.y, aH[3], aL[3]);
#pragma unroll
        for (int n8 = 0; n8 < 16; n8++) {
            const unsigned* pH = d_WEfH + (size_t)(n8 * 64 + c) * 64 + lane * 2;
            const unsigned* pL = d_WEfL + (size_t)(n8 * 64 + c) * 64 + lane * 2;
            unsigned bH[2], bL[2];
            *(uint2*)bH = *(const uint2*)pH;
            *(uint2*)bL = *(const uint2*)pL;
            mma16816(acc[n8], aH, bH);
            mma16816(acc[n8], aH, bL);
            mma16816(acc[n8], aL, bH);
        }
    }
    int row0 = m16 * 16 + lr;
#pragma unroll
    for (int n8 = 0; n8 < 16; n8++) {
        int col = n8 * 8 + lc * 2;
        *(float2*)(d_zbuf + (size_t)row0 * ZD + col)       = make_float2(acc[n8][0], acc[n8][1]);
        *(float2*)(d_zbuf + (size_t)(row0 + 8) * ZD + col) = make_float2(acc[n8][2], acc[n8][3]);
    }
}

// ------------------------- persistent recurrence ---------------------------
__global__ void __launch_bounds__(NT) recur(
    const float* __restrict__ b_key, const float* __restrict__ W_g,
    const float* __restrict__ b_g,   const float* __restrict__ W_y,
    const float* __restrict__ b_y,
    const float* __restrict__ gamma, const float* __restrict__ beta,
    const float* __restrict__ cgain, const float* __restrict__ cbias,
    void* outp, int out_size)
{
    extern __shared__ unsigned sS[];   // 4 buffers x 3 chunks x 3072 words

    const int tid = threadIdx.x;
    const int bx = blockIdx.x;
    const int lane = tid & 31, wid = tid >> 5;
    const int lr = lane >> 2, lc = lane & 3;

    const int mblk = bx >> 4, nblk = bx & 15;
    const int wmm = wid & 3;
    const int wn  = wid >> 2;
    const int m16g = mblk * 4 + wmm;

    const int t8      = tid & 255;
    const int a_plane = t8 >> 7;
    const int a_m16A  = mblk * 4 + ((t8 >> 5) & 3);
    const int a_widx  = (t8 & 31) * 4;
    const int a_soff  = a_plane * 512 + ((t8 >> 5) & 3) * 128 + a_widx;

    const int b_plane = tid >> 8;
    const int b_n8l   = (tid >> 4) & 15;
    const int b_w4    = (tid & 15) * 4;
    const int b_soff  = 1024 + b_plane * 1024 + b_n8l * 64 + b_w4;
    const unsigned* bSrc = (b_plane ? d_BfL : d_BfH) +
                           (size_t)(nblk * 16 + b_n8l) * (NCHP * 64) + b_w4;

    float4 bias4[4];
#pragma unroll
    for (int jj = 0; jj < 4; jj++) {
        int n8g = nblk * 16 + wn * 4 + jj;
        int jq = n8g * 2 + (lc >> 1);
        bias4[jj] = *(const float4*)(d_biasg + jq * 4);
    }

    const bool odd = (lc & 1);
    float cc4[4] = {0.f, 0.f, 0.f, 0.f};

    for (int t = 0; t < MD; t++) {
        const int cur = t & 1, pn = (t + 1) & 1;
        // ============ Phase A: gate GEMM + fused cell =======================
        {
            float acc[4][4];
#pragma unroll
            for (int j = 0; j < 4; j++)
#pragma unroll
                for (int r = 0; r < 4; r++) acc[j][r] = 0.f;

            if (t == 0) {
                // ---- t=0: GEMM is all-zero; use the slot for norm+attn -----
                float* zs = (float*)sS;            // TD*ZP floats
                float* S  = (float*)sS + TD * ZP;  // TD*TD floats
                const float cg = cgain[0], cb = cbias[0];
#pragma unroll 1
                for (int bi = 0; bi < 4; bi++) {
                    int b = bx * 4 + bi;
                    __syncthreads();
                    if (tid < 128) {
                        float v[TD];
                        float s = 0.f;
#pragma unroll
                        for (int tt = 0; tt < TD; tt++) {
                            v[tt] = d_zbuf[((size_t)(b * TD) + tt) * ZD + tid];
                            s += v[tt];
                        }
                        float mu = s * (1.f / TD);
                        float q = 0.f;
#pragma unroll
                        for (int tt = 0; tt < TD; tt++) { float d = v[tt] - mu; q += d * d; }
                        float inv = rsqrtf(q * (1.f / TD) + 1e-8f);
                        float ga = gamma[tid], be = beta[tid];
#pragma unroll
                        for (int tt = 0; tt < TD; tt++)
                            zs[tt * ZP + tid] = (v[tt] - mu) * inv * ga + be;
                    }
                    __syncthreads();
                    for (int p = tid; p < TD * TD; p += NT) {
                        int tt = p >> 5, m = p & 31;
                        if (m < tt) {
                            const float* zt = zs + tt * ZP;
                            const float* zm = zs + m * ZP;
                            float s = 0.f;
#pragma unroll 8
                            for (int i = 0; i < ZD; i++) s += zt[i] * zm[i];
                            S[p] = s;
                        }
                    }
                    __syncthreads();
#pragma unroll
                    for (int it = 0; it < 2; it++) {
                        int tt = 1 + wid + it * 16;
                        if (tt <= 31) {
                            float sv = (lane < tt) ? S[tt * TD + lane] : -3.4e38f;
                            float mx = sv;
#pragma unroll
                            for (int o = 16; o; o >>= 1)
                                mx = fmaxf(mx, __shfl_xor_sync(0xffffffffu, mx, o));
                            float e = (lane < tt) ? __expf(sv - mx) : 0.f;
                            float sum = e;
#pragma unroll
                            for (int o = 16; o; o >>= 1)
                                sum += __shfl_xor_sync(0xffffffffu, sum, o);
                            float inv = __fdividef(1.f, sum);
                            if (lane < tt) {
                                d_wk[((size_t)b * MD + tt) * MD + lane] = e * inv;
                                d_ck[((size_t)b * MD + tt) * MD + lane] = sigm(sv * cg + cb);
                            }
                        }
                    }
                }
                __syncthreads();
            } else {
                const unsigned* aSrc = (a_plane ? d_AfL[cur] : d_AfH[cur]) +
                                       (size_t)a_m16A * (NCHP * 128) + a_widx;
                // prologue: stage groups 0..2 (all h chunks) -- R13 placement
#pragma unroll
                for (int p = 0; p < 3; p++) {
#pragma unroll
                    for (int ccq = 0; ccq < 3; ccq++) {
                        int ch = ordc(p * 3 + ccq);
                        unsigned* dst = sS + (size_t)(p * 3 + ccq) * CHW;
                        if (tid < 256) cpasync16(dst + a_soff, aSrc + ch * 128);
                        cpasync16(dst + b_soff, bSrc + ch * 64);
                    }
                    CPCOMMIT();
                }

                int bufIdx = 0;
#pragma unroll 1
                for (int g = 0; g < NGRP; g++) {
                    int sg = g + 3;
                    CPWAIT(2);
                    __syncthreads();
                    if (sg == 10) {   // about to stage first key_r chunk
                        if (tid == 0) {
                            unsigned tgt = 128u * (unsigned)t;
                            while (*(volatile unsigned*)&g_kr < tgt) { __nanosleep(32); }
                            __threadfence();
                        }
                        __syncthreads();
                    }
                    if (sg < NGRP) {
                        int nbuf = bufIdx + 3; if (nbuf >= 4) nbuf -= 4;
                        int nsc = (sg == NGRP - 1) ? 1 : 3;   // last group: 1 real chunk
#pragma unroll
                        for (int ccq = 0; ccq < 3; ccq++) {
                            if (ccq < nsc) {
                                int ch = ordc(sg * 3 + ccq);
                                unsigned* dst = sS + (size_t)(nbuf * 3 + ccq) * CHW;
                                if (tid < 256) cpasync16(dst + a_soff, aSrc + ch * 128);
                                cpasync16(dst + b_soff, bSrc + ch * 64);
                            }
                        }
                    }
                    CPCOMMIT();
                    const unsigned* gb = sS + (size_t)bufIdx * 3 * CHW;
                    int ncc = (g == NGRP - 1) ? 1 : 3;   // last group: 1 real chunk
#pragma unroll
                    for (int ccq = 0; ccq < 3; ccq++) {
                        if (ccq >= ncc) break;
                        const unsigned* base = gb + ccq * CHW;
                        unsigned aH[4], aL[4];
                        *(uint4*)aH = *(const uint4*)(base + wmm * 128 + lane * 4);
                        *(uint4*)aL = *(const uint4*)(base + 512 + wmm * 128 + lane * 4);
                        unsigned bH[4][2], bL[4][2];
#pragma unroll
                        for (int jj = 0; jj < 4; jj++) {
                            *(uint2*)bH[jj] = *(const uint2*)(base + 1024 + (wn * 4 + jj) * 64 + lane * 2);
                            *(uint2*)bL[jj] = *(const uint2*)(base + 2048 + (wn * 4 + jj) * 64 + lane * 2);
                        }
#pragma unroll
                        for (int jj = 0; jj < 4; jj++) mma16816(acc[jj], aH, bH[jj]);
#pragma unroll
                        for (int jj = 0; jj < 4; jj++) mma16816(acc[jj], aH, bL[jj]);
#pragma unroll
                        for (int jj = 0; jj < 4; jj++) mma16816(acc[jj], aL, bH[jj]);
                    }
                    bufIdx++; if (bufIdx == 4) bufIdx = 0;
                }
            }

            // ---- fused epilogue: gates + cell update + h frag stores ----
            unsigned* hOutH = d_AfH[pn];
            unsigned* hOutL = d_AfL[pn];
#pragma unroll
            for (int jj = 0; jj < 4; jj++) {
                float a0 = acc[jj][0], a1 = acc[jj][1];
                float a2 = acc[jj][2], a3 = acc[jj][3];
                float p0 = __shfl_xor_sync(0xffffffffu, odd ? a0 : a2, 1);
                float p1 = __shfl_xor_sync(0xffffffffu, odd ? a1 : a3, 1);
                float4 bb4 = bias4[jj];
                float gi, gf, gg, go;
                if (!odd) { gi = a0 + bb4.x; gf = a1 + bb4.y; gg = p0 + bb4.z; go = p1 + bb4.w; }
                else      { gi = p0 + bb4.x; gf = p1 + bb4.y; gg = a2 + bb4.z; go = a3 + bb4.w; }
                float cn = sigm(gf) * cc4[jj] + sigm(gi) * tanhap(gg);
                cc4[jj] = cn;
                float hv = sigm(go) * tanhap(cn);
                int n8g = nblk * 16 + wn * 4 + jj;
                int jq = n8g * 2 + (lc >> 1);
                int row = m16g * 16 + lr + (odd ? 8 : 0);
                d_h[row * HD + jq] = hv;
                __nv_bfloat16 hh = __float2bfloat16_rn(hv);
                __nv_bfloat16 hl = __float2bfloat16_rn(hv - __bfloat162float(hh));
                unsigned uh = (unsigned)__bfloat16_as_ushort(hh);
                unsigned ul = (unsigned)__bfloat16_as_ushort(hl);
                unsigned ph = __shfl_xor_sync(0xffffffffu, uh, 2);
                unsigned pl = __shfl_xor_sync(0xffffffffu, ul, 2);
                if ((lc & 2) == 0) {
                    int kk = jq & 15;
                    int ch = 17 + (jq >> 4);
                    int lane_a = lr * 4 + ((kk & 7) >> 1);
                    int w = (odd ? 1 : 0) + ((kk >> 3) << 1);
                    size_t widx = ((size_t)(m16g * NCHP + ch)) * 128 + lane_a * 4 + w;
                    hOutH[widx] = (ph << 16) | uh;
                    hOutL[widx] = (pl << 16) | ul;
                }
            }
        }
        gridBarrier();  // h, Mk(t-1), (t=0: wk/ck) visible everywhere

        // ============ Phase C ==============================================
        if (t < TD) {
            if (bx < 64) {  // key_w = relu(h @ W_key^T + b_key), dual-chain
                const int m16 = (bx >> 3) * 4 + (wid & 3);
                const int n8  = (bx & 7) * 4 + (wid >> 2);
                const unsigned* pAH = d_AfH[pn] + ((size_t)m16 * NCHP + 17) * 128 + lane * 4;
                const unsigned* pAL = d_AfL[pn] + ((size_t)m16 * NCHP + 17) * 128 + lane * 4;
                const unsigned* pWH = d_WKfH + (size_t)n8 * (32 * 64) + lane * 2;
                const unsigned* pWL = d_WKfL + (size_t)n8 * (32 * 64) + lane * 2;
                float ka[4] = {0.f, 0.f, 0.f, 0.f};
                float kb[4] = {0.f, 0.f, 0.f, 0.f};
                unsigned cAH0[4], cAL0[4], cW0H[2], cW0L[2];
                unsigned cAH1[4], cAL1[4], cW1H[2], cW1L[2];
                *(uint4*)cAH0 = *(const uint4*)(pAH);
                *(uint4*)cAL0 = *(const uint4*)(pAL);
                *(uint2*)cW0H = *(const uint2*)(pWH);
                *(uint2*)cW0L = *(const uint2*)(pWL);
                *(uint4*)cAH1 = *(const uint4*)(pAH + 16 * 128);
                *(uint4*)cAL1 = *(const uint4*)(pAL + 16 * 128);
                *(uint2*)cW1H = *(const uint2*)(pWH + 16 * 64);
                *(uint2*)cW1L = *(const uint2*)(pWL + 16 * 64);
#pragma unroll 1
                for (int ch = 0; ch < 16; ch++) {
                    unsigned nAH0[4], nAL0[4], nW0H[2], nW0L[2];
                    unsigned nAH1[4], nAL1[4], nW1H[2], nW1L[2];
                    if (ch < 15) {
                        *(uint4*)nAH0 = *(const uint4*)(pAH + (ch + 1) * 128);
                        *(uint4*)nAL0 = *(const uint4*)(pAL + (ch + 1) * 128);
                        *(uint2*)nW0H = *(const uint2*)(pWH + (ch + 1) * 64);
                        *(uint2*)nW0L = *(const uint2*)(pWL + (ch + 1) * 64);
                        *(uint4*)nAH1 = *(const uint4*)(pAH + (ch + 17) * 128);
                        *(uint4*)nAL1 = *(const uint4*)(pAL + (ch + 17) * 128);
                        *(uint2*)nW1H = *(const uint2*)(pWH + (ch + 17) * 64);
                        *(uint2*)nW1L = *(const uint2*)(pWL + (ch + 17) * 64);
                    }
                    mma16816(ka, cAH0, cW0H);
                    mma16816(kb, cAH1, cW1H);
                    mma16816(ka, cAH0, cW0L);
                    mma16816(kb, cAH1, cW1L);
                    mma16816(ka, cAL0, cW0H);
                    mma16816(kb, cAL1, cW1H);
                    if (ch < 15) {
                        *(uint4*)cAH0 = *(uint4*)nAH0; *(uint4*)cAL0 = *(uint4*)nAL0;
                        *(uint2*)cW0H = *(uint2*)nW0H; *(uint2*)cW0L = *(uint2*)nW0L;
                        *(uint4*)cAH1 = *(uint4*)nAH1; *(uint4*)cAL1 = *(uint4*)nAL1;
                        *(uint2*)cW1H = *(uint2*)nW1H; *(uint2*)cW1L = *(uint2*)nW1L;
                    }
                }
#pragma unroll
                for (int r = 0; r < 4; r++) ka[r] += kb[r];
                int col = n8 * 8 + lc * 2;
                float bk0 = b_key[col], bk1 = b_key[col + 1];
                int row0 = m16 * 16 + lr;
                float2 v0 = {fmaxf(ka[0] + bk0, 0.f), fmaxf(ka[1] + bk1, 0.f)};
                float2 v1 = {fmaxf(ka[2] + bk0, 0.f), fmaxf(ka[3] + bk1, 0.f)};
                *(float2*)(d_Mk + ((size_t)row0 * MD + t) * KD + col) = v0;
                *(float2*)(d_Mk + ((size_t)(row0 + 8) * MD + t) * KD + col) = v1;
            } else {  // gate g + attention read -> key_r fragments (parity pn)
                int bb = (bx - 64) * 8 + (wid & 7);
                const float* hb = d_h + (size_t)bb * HD;
                float s = 0.f;
                for (int l = lane; l < HD; l += 32) s += hb[l] * W_g[l];
#pragma unroll
                for (int o = 16; o; o >>= 1) s += __shfl_xor_sync(0xffffffffu, s, o);
                float gv = sigm(s + b_g[0]);
                const float* wkb = d_wk + ((size_t)bb * MD + t) * MD;
                const float* ckb = d_ck + ((size_t)bb * MD + t) * MD;
                const float* mkb = d_Mk + (size_t)bb * MD * KD;
                int m16 = bb >> 4, r = bb & 15;
                unsigned* oH = d_AfH[pn];
                unsigned* oL = d_AfL[pn];
                for (int dp = lane + ((wid >> 3) << 5); dp < 129; dp += 64) {
                    int d0 = dp * 2;
                    float v0 = 0.f, v1 = 0.f;
                    if (d0 < 256) {
                        int m = 0;
                        for (; m + 4 <= t; m += 4) {
                            float w0 = wkb[m], w1 = wkb[m + 1];
                            float w2 = wkb[m + 2], w3 = wkb[m + 3];
                            float x0 = mkb[(m) * KD + d0],     y0 = mkb[(m) * KD + d0 + 1];
                            float x1 = mkb[(m + 1) * KD + d0], y1 = mkb[(m + 1) * KD + d0 + 1];
                            float x2 = mkb[(m + 2) * KD + d0], y2 = mkb[(m + 2) * KD + d0 + 1];
                            float x3 = mkb[(m + 3) * KD + d0], y3 = mkb[(m + 3) * KD + d0 + 1];
                            v0 += w0 * x0 + w1 * x1 + w2 * x2 + w3 * x3;
                            v1 += w0 * y0 + w1 * y1 + w2 * y2 + w3 * y3;
                        }
                        for (; m < t; m++) {
                            float w = wkb[m];
                            v0 += w * mkb[m * KD + d0];
                            v1 += w * mkb[m * KD + d0 + 1];
                        }
                    } else {
                        for (int m = 0; m < t; m++) v0 += wkb[m] * ckb[m];
                    }
                    v0 *= gv; v1 *= gv;
                    __nv_bfloat16 h0 = __float2bfloat16_rn(v0);
                    __nv_bfloat16 h1 = __float2bfloat16_rn(v1);
                    int ch = d0 >> 4, kk = d0 & 15;
                    int lane_a = (r & 7) * 4 + ((kk & 7) >> 1);
                    int w = (r >> 3) + ((kk >> 3) << 1);
                    size_t widx = ((size_t)(m16 * NCHP + ch)) * 128 + lane_a * 4 + w;
                    oH[widx] = (unsigned)__bfloat16_as_ushort(h1) << 16 |
                               __bfloat16_as_ushort(h0);
                    oL[widx] = packbf2(v0 - __bfloat162float(h0),
                                       v1 - __bfloat162float(h1));
                }
            }
            // producer arrival: key_r (and Mk) for step t complete on this block
            __syncthreads();
            if (tid == 0) { __threadfence(); atomicAdd(&g_kr, 1u); }
        } else {  // t == 32: y_lin + argmax
            if (bx >= 64 && bx < 128 && wid < 8) {
                int bb = (bx - 64) * 8 + wid;
                const float* hb = d_h + (size_t)bb * HD;
                float yv[4];
#pragma unroll
                for (int yi = 0; yi < YD; yi++) {
                    float s = 0.f;
                    for (int l = lane; l < HD; l += 32) s += hb[l] * W_y[yi * HD + l];
#pragma unroll
                    for (int o = 16; o; o >>= 1) s += __shfl_xor_sync(0xffffffffu, s, o);
                    yv[yi] = s + b_y[yi];
                }
                if (lane == 0) {
                    int am = 0; float bst = yv[0];
#pragma unroll
                    for (int yi = 1; yi < YD; yi++)
                        if (yv[yi] > bst) { bst = yv[yi]; am = yi; }
                    if (out_size >= BD * YD) {
                        float* of = (float*)outp;
                        of[bb * 4 + 0] = yv[0];
                        of[bb * 4 + 1] = yv[1];
                        of[bb * 4 + 2] = yv[2];
                        of[bb * 4 + 3] = yv[3];
                        if (out_size >= BD * YD + BD) of[BD * YD + bb] = (float)am;
                    } else {
                        ((int*)outp)[bb] = am;
                    }
                }
            }
        }
    }
}

// ------------------------------- launcher ----------------------------------
extern "C" void kernel_launch(void* const* d_in, const int* in_sizes, int n_in,
                              void* d_out, int out_size)
{
    const float* x_seq  = (const float*)d_in[0];
    const float* W_enc  = (const float*)d_in[1];
    const float* gamma  = (const float*)d_in[2];
    const float* beta   = (const float*)d_in[3];
    const float* W_ih   = (const float*)d_in[4];
    const float* W_hh   = (const float*)d_in[5];
    const float* b_ih   = (const float*)d_in[6];
    const float* b_hh   = (const float*)d_in[7];
    const float* W_key  = (const float*)d_in[8];
    const float* b_key  = (const float*)d_in[9];
    const float* W_g    = (const float*)d_in[10];
    const float* b_g    = (const float*)d_in[11];
    const float* cgain  = (const float*)d_in[12];
    const float* cbias  = (const float*)d_in[13];
    const float* W_y    = (const float*)d_in[14];
    const float* b_y    = (const float*)d_in[15];

    cudaFuncSetAttribute(recur, cudaFuncAttributeMaxDynamicSharedMemorySize,
                         SMEM_RECUR);

    prep_kernel<<<1024, 256>>>(W_ih, W_hh, b_ih, b_hh, W_key, W_enc);
    enc_gemm2<<<128, 256>>>(x_seq);
    recur<<<NB, NT, SMEM_RECUR>>>(b_key, W_g, b_g, W_y, b_y,
                                  gamma, beta, cgain, cbias, d_out, out_size);
}

// round 17
// speedup vs baseline: 1.1230x; 1.1101x over previous
#include <cuda_runtime.h>
#include <cuda_bf16.h>
#include <math.h>

// ---------------------------------------------------------------------------
// Model_24730421690434  (R16)
//   B=512, T=32, Z=128, K=256, H=512, 4H=2048, Y=4, M=33
// R16: byte-exact R13 (recur, prep, norm_attn) + enc_gemm2 W-operand staged
//      through smem (3-stage cp.async, kills 8x redundant L2 reads of W).
// ---------------------------------------------------------------------------

#define NB 128
#define NT 512

#define BD 512
#define TD 32
#define ZD 128
#define KD 256
#define HD 512
#define YD 4
#define MD 33
#define G4 2048
#define NCHP 51     // chunk space: 0..16 key_r, 17..48 h, 49..50 zero pad
#define NGRP 17     // 17 groups x 3 chunks (last group: only 1 real chunk)
#define ZP 129
#define CHW 3072    // words/staged chunk: A[0,1024) | Bhi[1024,2048) | Blo[2048,3072)
#define SMEM_RECUR (12 * CHW * 4)   // 4 buffers x 3 chunks = 144 KB

// ------------------------------- device state ------------------------------
__device__ __align__(256) unsigned d_BfH[256 * NCHP * 64];
__device__ __align__(256) unsigned d_BfL[256 * NCHP * 64];
__device__ __align__(256) unsigned d_WKfH[32 * 32 * 64];
__device__ __align__(256) unsigned d_WKfL[32 * 32 * 64];
__device__ __align__(256) unsigned d_WEfH[16 * 64 * 64];
__device__ __align__(256) unsigned d_WEfL[16 * 64 * 64];
__device__ __align__(256) unsigned d_AfH[2][32 * NCHP * 128];
__device__ __align__(256) unsigned d_AfL[2][32 * NCHP * 128];

__device__ __align__(256) float d_biasg[G4];
__device__ __align__(256) float d_zbuf[BD * TD * ZD];
__device__ __align__(256) float d_h[BD * HD];
__device__ __align__(256) float d_Mk[(size_t)BD * MD * KD];
__device__ __align__(256) float d_wk[(size_t)BD * MD * MD];
__device__ __align__(256) float d_ck[(size_t)BD * MD * MD];
__device__ unsigned g_cnt1[8 * 32];
__device__ unsigned g_cnt2;
__device__ unsigned g_gen;
__device__ unsigned g_kr;          // key_r producer arrivals (reset in prep)

// reordered chunk index: h chunks (17..48) first, then key_r (0..16), pads
__device__ __forceinline__ int ordc(int i) {
    return (i < 32) ? (17 + i) : ((i < 49) ? (i - 32) : i);
}

__device__ __forceinline__ float tanhap(float x) {
    float y; asm("tanh.approx.f32 %0, %1;" : "=f"(y) : "f"(x)); return y;
}
__device__ __forceinline__ float sigm(float x) {
    return fmaf(tanhap(x * 0.5f), 0.5f, 0.5f);
}

__device__ __forceinline__ void gridBarrier() {
    __syncthreads();
    if (threadIdx.x == 0) {
        const int grp = (blockIdx.x & 7) * 32;
        unsigned gen = *(volatile unsigned*)&g_gen;
        __threadfence();
        if (atomicAdd(&g_cnt1[grp], 1u) == 15u) {
            g_cnt1[grp] = 0u;
            __threadfence();
            if (atomicAdd(&g_cnt2, 1u) == 7u) {
                g_cnt2 = 0u;
                __threadfence();
                atomicAdd(&g_gen, 1u);
            }
        }
        while (*(volatile unsigned*)&g_gen == gen) { __nanosleep(32); }
        __threadfence();
    }
    __syncthreads();
}

__device__ __forceinline__ void cpasync16(void* dst, const void* src) {
    unsigned saddr = (unsigned)__cvta_generic_to_shared(dst);
    asm volatile("cp.async.cg.shared.global [%0], [%1], 16;\n" ::"r"(saddr), "l"(src));
}
#define CPCOMMIT() asm volatile("cp.async.commit_group;\n" ::)
#define CPWAIT(n)  asm volatile("cp.async.wait_group %0;\n" ::"n"(n))

__device__ __forceinline__ void mma16816(float* d, const unsigned* a, const unsigned* b) {
    asm volatile(
        "mma.sync.aligned.m16n8k16.row.col.f32.bf16.bf16.f32 "
        "{%0,%1,%2,%3},{%4,%5,%6,%7},{%8,%9},{%0,%1,%2,%3};"
        : "+f"(d[0]), "+f"(d[1]), "+f"(d[2]), "+f"(d[3])
        : "r"(a[0]), "r"(a[1]), "r"(a[2]), "r"(a[3]), "r"(b[0]), "r"(b[1]));
}

__device__ __forceinline__ unsigned packbf2(float v0, float v1) {
    unsigned short u0 = __bfloat16_as_ushort(__float2bfloat16_rn(v0));
    unsigned short u1 = __bfloat16_as_ushort(__float2bfloat16_rn(v1));
    return (unsigned)u1 << 16 | u0;
}
__device__ __forceinline__ void splitbf2(float v0, float v1, unsigned& hi, unsigned& lo) {
    __nv_bfloat16 h0 = __float2bfloat16_rn(v0);
    __nv_bfloat16 h1 = __float2bfloat16_rn(v1);
    hi = (unsigned)__bfloat16_as_ushort(h1) << 16 | __bfloat16_as_ushort(h0);
    lo = packbf2(v0 - __bfloat162float(h0), v1 - __bfloat162float(h1));
}

// ------------------------------- prep kernel -------------------------------
__device__ __forceinline__ float fetchW(const float* W_ih, const float* W_hh,
                                        int n, int k) {
    if (k < 257) return W_ih[n * 257 + k];
    if (k >= 272 && k < 784) return W_hh[n * HD + (k - 272)];
    return 0.f;
}

__global__ void __launch_bounds__(256) prep_kernel(
    const float* __restrict__ W_ih, const float* __restrict__ W_hh,
    const float* __restrict__ b_ih, const float* __restrict__ b_hh,
    const float* __restrict__ W_key, const float* __restrict__ W_enc)
{
    const int stride = gridDim.x * blockDim.x;
    const int gtid = blockIdx.x * blockDim.x + threadIdx.x;
    if (gtid == 0) g_kr = 0u;

    for (int idx = gtid; idx < 256 * NCHP * 64; idx += stride) {
        int n8 = idx / (NCHP * 64);
        int rem = idx - n8 * (NCHP * 64);
        int c = rem >> 6;
        int lw = rem & 63;
        int lane = lw >> 1, w = lw & 1;
        int lr = lane >> 2, lc = lane & 3;
        int np = n8 * 8 + lr;
        int g = np & 3, j = np >> 2;
        int orig = g * 512 + j;
        int k = c * 16 + w * 8 + lc * 2;
        float v0 = (k < 784) ? fetchW(W_ih, W_hh, orig, k) : 0.f;
        float v1 = (k + 1 < 784) ? fetchW(W_ih, W_hh, orig, k + 1) : 0.f;
        splitbf2(v0, v1, d_BfH[idx], d_BfL[idx]);
    }
    for (int idx = gtid; idx < 32 * 32 * 64; idx += stride) {
        int n8 = idx / (32 * 64);
        int rem = idx - n8 * (32 * 64);
        int c = rem >> 6;
        int lw = rem & 63;
        int lane = lw >> 1, w = lw & 1;
        int lr = lane >> 2, lc = lane & 3;
        int n = n8 * 8 + lr;
        int k = c * 16 + w * 8 + lc * 2;
        splitbf2(W_key[n * HD + k], W_key[n * HD + k + 1],
                 d_WKfH[idx], d_WKfL[idx]);
    }
    for (int idx = gtid; idx < 16 * 64 * 64; idx += stride) {
        int n8 = idx / (64 * 64);
        int rem = idx - n8 * (64 * 64);
        int c = rem >> 6;
        int lw = rem & 63;
        int lane = lw >> 1, w = lw & 1;
        int lr = lane >> 2, lc = lane & 3;
        int n = n8 * 8 + lr;
        int k = c * 16 + w * 8 + lc * 2;
        splitbf2(W_enc[k * ZD + n], W_enc[(k + 1) * ZD + n],
                 d_WEfH[idx], d_WEfL[idx]);
    }
    for (int np = gtid; np < G4; np += stride) {
        int orig = (np & 3) * 512 + (np >> 2);
        d_biasg[np] = b_ih[orig] + b_hh[orig];
    }
    // zero ONLY the pad chunks (49,50)
    for (int idx = gtid; idx < 32 * 2 * 128; idx += stride) {
        int m16 = idx >> 8;
        int r = idx & 255;
        int ch = 49 + (r >> 7);
        int wq = r & 127;
        size_t off = ((size_t)(m16 * NCHP + ch)) * 128 + wq;
        d_AfH[0][off] = 0u; d_AfL[0][off] = 0u;
        d_AfH[1][off] = 0u; d_AfL[1][off] = 0u;
    }
}

// ------------------- encoder GEMM on tensor cores --------------------------
// R16: W fragments staged through smem (3-stage cp.async) so the 8 warps of a
// block share one L2 read per chunk instead of 8 redundant ones.
__global__ void __launch_bounds__(256) enc_gemm2(const float* __restrict__ X)
{
    __shared__ __align__(16) unsigned sW[3][2048];  // [stage][hi 1024 | lo 1024]
    const int tid = threadIdx.x;
    const int lane = tid & 31, wid = tid >> 5;
    const int lr = lane >> 2, lc = lane & 3;
    const int m16 = blockIdx.x * 8 + wid;

    // staging map: thread covers (n8 = tid>>4, 4 words at (tid&15)*4), 2 planes
    const int s_n8 = tid >> 4;
    const int s_lw = (tid & 15) * 4;
    const int s_off = s_n8 * 64 + s_lw;
    const unsigned* srcH = d_WEfH + (size_t)s_n8 * (64 * 64) + s_lw;
    const unsigned* srcL = d_WEfL + (size_t)s_n8 * (64 * 64) + s_lw;

    const float* xr0 = X + (size_t)(m16 * 16 + lr) * 1024;
    const float* xr1 = xr0 + 8 * 1024;

    float acc[16][4];
#pragma unroll
    for (int n8 = 0; n8 < 16; n8++)
#pragma unroll
        for (int r = 0; r < 4; r++) acc[n8][r] = 0.f;

    // prologue: stage chunks 0,1
#pragma unroll
    for (int p = 0; p < 2; p++) {
        cpasync16(&sW[p][s_off], srcH + p * 64);
        cpasync16(&sW[p][1024 + s_off], srcL + p * 64);
        CPCOMMIT();
    }

#pragma unroll 1
    for (int c = 0; c < 64; c++) {
        CPWAIT(1);
        __syncthreads();
        if (c + 2 < 64) {
            int st = c + 2; while (st >= 3) st -= 3;
            cpasync16(&sW[st][s_off], srcH + (c + 2) * 64);
            cpasync16(&sW[st][1024 + s_off], srcL + (c + 2) * 64);
        }
        CPCOMMIT();

        int cs = c; while (cs >= 3) cs -= 3;
        const unsigned* wb = sW[cs];

        int k = c * 16 + lc * 2;
        float2 x00 = *(const float2*)(xr0 + k);
        float2 x10 = *(const float2*)(xr1 + k);
        float2 x01 = *(const float2*)(xr0 + k + 8);
        float2 x11 = *(const float2*)(xr1 + k + 8);
        unsigned aH[4], aL[4];
        splitbf2(x00.x, x00.y, aH[0], aL[0]);
        splitbf2(x10.x, x10.y, aH[1], aL[1]);
        splitbf2(x01.x, x01.y, aH[2], aL[2]);
        splitbf2(x11.x, x11.y, aH[3], aL[3]);
#pragma unroll
        for (int n8 = 0; n8 < 16; n8++) {
            unsigned bH[2], bL[2];
            *(uint2*)bH = *(const uint2*)(wb + n8 * 64 + lane * 2);
            *(uint2*)bL = *(const uint2*)(wb + 1024 + n8 * 64 + lane * 2);
            mma16816(acc[n8], aH, bH);
            mma16816(acc[n8], aH, bL);
            mma16816(acc[n8], aL, bH);
        }
    }
    int row0 = m16 * 16 + lr;
#pragma unroll
    for (int n8 = 0; n8 < 16; n8++) {
        int col = n8 * 8 + lc * 2;
        *(float2*)(d_zbuf + (size_t)row0 * ZD + col)       = make_float2(acc[n8][0], acc[n8][1]);
        *(float2*)(d_zbuf + (size_t)(row0 + 8) * ZD + col) = make_float2(acc[n8][2], acc[n8][3]);
    }
}

// ------- fused context norm + attention precompute (per batch block) -------
__global__ void __launch_bounds__(256) norm_attn(
    const float* __restrict__ gamma, const float* __restrict__ beta,
    const float* __restrict__ cgain, const float* __restrict__ cbias)
{
    __shared__ float zs[TD * ZP];
    __shared__ float S[TD * TD];
    const int b = blockIdx.x, tid = threadIdx.x;
    const int lane = tid & 31, w = tid >> 5;

    if (tid < 128) {
        float v[TD];
        float s = 0.f;
#pragma unroll
        for (int t = 0; t < TD; t++) {
            v[t] = d_zbuf[((size_t)(b * TD) + t) * ZD + tid];
            s += v[t];
        }
        float mu = s * (1.f / TD);
        float q = 0.f;
#pragma unroll
        for (int t = 0; t < TD; t++) { float d = v[t] - mu; q += d * d; }
        float inv = rsqrtf(q * (1.f / TD) + 1e-8f);
        float ga = gamma[tid], be = beta[tid];
#pragma unroll
        for (int t = 0; t < TD; t++)
            zs[t * ZP + tid] = (v[t] - mu) * inv * ga + be;
    }
    __syncthreads();

    const float cg = cgain[0], cb = cbias[0];
    for (int p = tid; p < TD * TD; p += 256) {
        int t = p >> 5, m = p & 31;
        if (m < t) {
            const float* zt = zs + t * ZP;
            const float* zm = zs + m * ZP;
            float s = 0.f;
#pragma unroll 8
            for (int i = 0; i < ZD; i++) s += zt[i] * zm[i];
            S[p] = s;
        }
    }
    __syncthreads();
#pragma unroll
    for (int it = 0; it < 4; it++) {
        int t = 1 + w + it * 8;
        if (t > 31) break;
        float sv = (lane < t) ? S[t * TD + lane] : -3.4e38f;
        float mx = sv;
#pragma unroll
        for (int o = 16; o; o >>= 1) mx = fmaxf(mx, __shfl_xor_sync(0xffffffffu, mx, o));
        float e = (lane < t) ? __expf(sv - mx) : 0.f;
        float sum = e;
#pragma unroll
        for (int o = 16; o; o >>= 1) sum += __shfl_xor_sync(0xffffffffu, sum, o);
        float inv = __fdividef(1.f, sum);
        if (lane < t) {
            d_wk[((size_t)b * MD + t) * MD + lane] = e * inv;
            d_ck[((size_t)b * MD + t) * MD + lane] = sigm(sv * cg + cb);
        }
    }
}

// ------------------------- persistent recurrence ---------------------------
__global__ void __launch_bounds__(NT) recur(
    const float* __restrict__ b_key, const float* __restrict__ W_g,
    const float* __restrict__ b_g,   const float* __restrict__ W_y,
    const float* __restrict__ b_y,   void* outp, int out_size)
{
    extern __shared__ unsigned sS[];   // 4 buffers x 3 chunks x 3072 words

    const int tid = threadIdx.x;
    const int bx = blockIdx.x;
    const int lane = tid & 31, wid = tid >> 5;
    const int lr = lane >> 2, lc = lane & 3;

    const int mblk = bx >> 4, nblk = bx & 15;
    const int wmm = wid & 3;
    const int wn  = wid >> 2;
    const int m16g = mblk * 4 + wmm;

    const int t8      = tid & 255;
    const int a_plane = t8 >> 7;
    const int a_m16A  = mblk * 4 + ((t8 >> 5) & 3);
    const int a_widx  = (t8 & 31) * 4;
    const int a_soff  = a_plane * 512 + ((t8 >> 5) & 3) * 128 + a_widx;

    const int b_plane = tid >> 8;
    const int b_n8l   = (tid >> 4) & 15;
    const int b_w4    = (tid & 15) * 4;
    const int b_soff  = 1024 + b_plane * 1024 + b_n8l * 64 + b_w4;
    const unsigned* bSrc = (b_plane ? d_BfL : d_BfH) +
                           (size_t)(nblk * 16 + b_n8l) * (NCHP * 64) + b_w4;

    float4 bias4[4];
#pragma unroll
    for (int jj = 0; jj < 4; jj++) {
        int n8g = nblk * 16 + wn * 4 + jj;
        int jq = n8g * 2 + (lc >> 1);
        bias4[jj] = *(const float4*)(d_biasg + jq * 4);
    }

    const bool odd = (lc & 1);
    float cc4[4] = {0.f, 0.f, 0.f, 0.f};

    for (int t = 0; t < MD; t++) {
        const int cur = t & 1, pn = (t + 1) & 1;
        // ============ Phase A: gate GEMM + fused cell =======================
        {
            float acc[4][4];
#pragma unroll
            for (int j = 0; j < 4; j++)
#pragma unroll
                for (int r = 0; r < 4; r++) acc[j][r] = 0.f;

            if (t > 0) {   // t==0: inputs all zero -> gates = bias only
                const unsigned* aSrc = (a_plane ? d_AfL[cur] : d_AfH[cur]) +
                                       (size_t)a_m16A * (NCHP * 128) + a_widx;
                // prologue: stage groups 0..2 (all h chunks)
#pragma unroll
                for (int p = 0; p < 3; p++) {
#pragma unroll
                    for (int ccq = 0; ccq < 3; ccq++) {
                        int ch = ordc(p * 3 + ccq);
                        unsigned* dst = sS + (size_t)(p * 3 + ccq) * CHW;
                        if (tid < 256) cpasync16(dst + a_soff, aSrc + ch * 128);
                        cpasync16(dst + b_soff, bSrc + ch * 64);
                    }
                    CPCOMMIT();
                }

                int bufIdx = 0;
#pragma unroll 1
                for (int g = 0; g < NGRP; g++) {
                    int sg = g + 3;
                    CPWAIT(2);
                    __syncthreads();
                    if (sg == 10) {   // about to stage first key_r chunk
                        if (tid == 0) {
                            unsigned tgt = 128u * (unsigned)t;
                            while (*(volatile unsigned*)&g_kr < tgt) { __nanosleep(32); }
                            __threadfence();
                        }
                        __syncthreads();
                    }
                    if (sg < NGRP) {
                        int nbuf = bufIdx + 3; if (nbuf >= 4) nbuf -= 4;
                        int nsc = (sg == NGRP - 1) ? 1 : 3;   // last group: 1 real chunk
#pragma unroll
                        for (int ccq = 0; ccq < 3; ccq++) {
                            if (ccq < nsc) {
                                int ch = ordc(sg * 3 + ccq);
                                unsigned* dst = sS + (size_t)(nbuf * 3 + ccq) * CHW;
                                if (tid < 256) cpasync16(dst + a_soff, aSrc + ch * 128);
                                cpasync16(dst + b_soff, bSrc + ch * 64);
                            }
                        }
                    }
                    CPCOMMIT();
                    const unsigned* gb = sS + (size_t)bufIdx * 3 * CHW;
                    int ncc = (g == NGRP - 1) ? 1 : 3;   // last group: 1 real chunk
#pragma unroll
                    for (int ccq = 0; ccq < 3; ccq++) {
                        if (ccq >= ncc) break;
                        const unsigned* base = gb + ccq * CHW;
                        unsigned aH[4], aL[4];
                        *(uint4*)aH = *(const uint4*)(base + wmm * 128 + lane * 4);
                        *(uint4*)aL = *(const uint4*)(base + 512 + wmm * 128 + lane * 4);
                        unsigned bH[4][2], bL[4][2];
#pragma unroll
                        for (int jj = 0; jj < 4; jj++) {
                            *(uint2*)bH[jj] = *(const uint2*)(base + 1024 + (wn * 4 + jj) * 64 + lane * 2);
                            *(uint2*)bL[jj] = *(const uint2*)(base + 2048 + (wn * 4 + jj) * 64 + lane * 2);
                        }
#pragma unroll
                        for (int jj = 0; jj < 4; jj++) mma16816(acc[jj], aH, bH[jj]);
#pragma unroll
                        for (int jj = 0; jj < 4; jj++) mma16816(acc[jj], aH, bL[jj]);
#pragma unroll
                        for (int jj = 0; jj < 4; jj++) mma16816(acc[jj], aL, bH[jj]);
                    }
                    bufIdx++; if (bufIdx == 4) bufIdx = 0;
                }
            }

            // ---- fused epilogue: gates + cell update + h frag stores ----
            unsigned* hOutH = d_AfH[pn];
            unsigned* hOutL = d_AfL[pn];
#pragma unroll
            for (int jj = 0; jj < 4; jj++) {
                float a0 = acc[jj][0], a1 = acc[jj][1];
                float a2 = acc[jj][2], a3 = acc[jj][3];
                float p0 = __shfl_xor_sync(0xffffffffu, odd ? a0 : a2, 1);
                float p1 = __shfl_xor_sync(0xffffffffu, odd ? a1 : a3, 1);
                float4 bb4 = bias4[jj];
                float gi, gf, gg, go;
                if (!odd) { gi = a0 + bb4.x; gf = a1 + bb4.y; gg = p0 + bb4.z; go = p1 + bb4.w; }
                else      { gi = p0 + bb4.x; gf = p1 + bb4.y; gg = a2 + bb4.z; go = a3 + bb4.w; }
                float cn = sigm(gf) * cc4[jj] + sigm(gi) * tanhap(gg);
                cc4[jj] = cn;
                float hv = sigm(go) * tanhap(cn);
                int n8g = nblk * 16 + wn * 4 + jj;
                int jq = n8g * 2 + (lc >> 1);
                int row = m16g * 16 + lr + (odd ? 8 : 0);
                d_h[row * HD + jq] = hv;
                __nv_bfloat16 hh = __float2bfloat16_rn(hv);
                __nv_bfloat16 hl = __float2bfloat16_rn(hv - __bfloat162float(hh));
                unsigned uh = (unsigned)__bfloat16_as_ushort(hh);
                unsigned ul = (unsigned)__bfloat16_as_ushort(hl);
                unsigned ph = __shfl_xor_sync(0xffffffffu, uh, 2);
                unsigned pl = __shfl_xor_sync(0xffffffffu, ul, 2);
                if ((lc & 2) == 0) {
                    int kk = jq & 15;
                    int ch = 17 + (jq >> 4);
                    int lane_a = lr * 4 + ((kk & 7) >> 1);
                    int w = (odd ? 1 : 0) + ((kk >> 3) << 1);
                    size_t widx = ((size_t)(m16g * NCHP + ch)) * 128 + lane_a * 4 + w;
                    hOutH[widx] = (ph << 16) | uh;
                    hOutL[widx] = (pl << 16) | ul;
                }
            }
        }
        gridBarrier();  // h, Mk(t-1) visible everywhere

        // ============ Phase C ==============================================
        if (t < TD) {
            if (bx < 64) {  // key_w = relu(h @ W_key^T + b_key), dual-chain
                const int m16 = (bx >> 3) * 4 + (wid & 3);
                const int n8  = (bx & 7) * 4 + (wid >> 2);
                const unsigned* pAH = d_AfH[pn] + ((size_t)m16 * NCHP + 17) * 128 + lane * 4;
                const unsigned* pAL = d_AfL[pn] + ((size_t)m16 * NCHP + 17) * 128 + lane * 4;
                const unsigned* pWH = d_WKfH + (size_t)n8 * (32 * 64) + lane * 2;
                const unsigned* pWL = d_WKfL + (size_t)n8 * (32 * 64) + lane * 2;
                float ka[4] = {0.f, 0.f, 0.f, 0.f};
                float kb[4] = {0.f, 0.f, 0.f, 0.f};
                unsigned cAH0[4], cAL0[4], cW0H[2], cW0L[2];
                unsigned cAH1[4], cAL1[4], cW1H[2], cW1L[2];
                *(uint4*)cAH0 = *(const uint4*)(pAH);
                *(uint4*)cAL0 = *(const uint4*)(pAL);
                *(uint2*)cW0H = *(const uint2*)(pWH);
                *(uint2*)cW0L = *(const uint2*)(pWL);
                *(uint4*)cAH1 = *(const uint4*)(pAH + 16 * 128);
                *(uint4*)cAL1 = *(const uint4*)(pAL + 16 * 128);
                *(uint2*)cW1H = *(const uint2*)(pWH + 16 * 64);
                *(uint2*)cW1L = *(const uint2*)(pWL + 16 * 64);
#pragma unroll 1
                for (int ch = 0; ch < 16; ch++) {
                    unsigned nAH0[4], nAL0[4], nW0H[2], nW0L[2];
                    unsigned nAH1[4], nAL1[4], nW1H[2], nW1L[2];
                    if (ch < 15) {
                        *(uint4*)nAH0 = *(const uint4*)(pAH + (ch + 1) * 128);
                        *(uint4*)nAL0 = *(const uint4*)(pAL + (ch + 1) * 128);
                        *(uint2*)nW0H = *(const uint2*)(pWH + (ch + 1) * 64);
                        *(uint2*)nW0L = *(const uint2*)(pWL + (ch + 1) * 64);
                        *(uint4*)nAH1 = *(const uint4*)(pAH + (ch + 17) * 128);
                        *(uint4*)nAL1 = *(const uint4*)(pAL + (ch + 17) * 128);
                        *(uint2*)nW1H = *(const uint2*)(pWH + (ch + 17) * 64);
                        *(uint2*)nW1L = *(const uint2*)(pWL + (ch + 17) * 64);
                    }
                    mma16816(ka, cAH0, cW0H);
                    mma16816(kb, cAH1, cW1H);
                    mma16816(ka, cAH0, cW0L);
                    mma16816(kb, cAH1, cW1L);
                    mma16816(ka, cAL0, cW0H);
                    mma16816(kb, cAL1, cW1H);
                    if (ch < 15) {
                        *(uint4*)cAH0 = *(uint4*)nAH0; *(uint4*)cAL0 = *(uint4*)nAL0;
                        *(uint2*)cW0H = *(uint2*)nW0H; *(uint2*)cW0L = *(uint2*)nW0L;
                        *(uint4*)cAH1 = *(uint4*)nAH1; *(uint4*)cAL1 = *(uint4*)nAL1;
                        *(uint2*)cW1H = *(uint2*)nW1H; *(uint2*)cW1L = *(uint2*)nW1L;
                    }
                }
#pragma unroll
                for (int r = 0; r < 4; r++) ka[r] += kb[r];
                int col = n8 * 8 + lc * 2;
                float bk0 = b_key[col], bk1 = b_key[col + 1];
                int row0 = m16 * 16 + lr;
                float2 v0 = {fmaxf(ka[0] + bk0, 0.f), fmaxf(ka[1] + bk1, 0.f)};
                float2 v1 = {fmaxf(ka[2] + bk0, 0.f), fmaxf(ka[3] + bk1, 0.f)};
                *(float2*)(d_Mk + ((size_t)row0 * MD + t) * KD + col) = v0;
                *(float2*)(d_Mk + ((size_t)(row0 + 8) * MD + t) * KD + col) = v1;
            } else {  // gate g + attention read -> key_r fragments (parity pn)
                int bb = (bx - 64) * 8 + (wid & 7);
                const float* hb = d_h + (size_t)bb * HD;
                float s = 0.f;
                for (int l = lane; l < HD; l += 32) s += hb[l] * W_g[l];
#pragma unroll
                for (int o = 16; o; o >>= 1) s += __shfl_xor_sync(0xffffffffu, s, o);
                float gv = sigm(s + b_g[0]);
                const float* wkb = d_wk + ((size_t)bb * MD + t) * MD;
                const float* ckb = d_ck + ((size_t)bb * MD + t) * MD;
                const float* mkb = d_Mk + (size_t)bb * MD * KD;
                int m16 = bb >> 4, r = bb & 15;
                unsigned* oH = d_AfH[pn];
                unsigned* oL = d_AfL[pn];
                for (int dp = lane + ((wid >> 3) << 5); dp < 129; dp += 64) {
                    int d0 = dp * 2;
                    float v0 = 0.f, v1 = 0.f;
                    if (d0 < 256) {
                        int m = 0;
                        for (; m + 4 <= t; m += 4) {
                            float w0 = wkb[m], w1 = wkb[m + 1];
                            float w2 = wkb[m + 2], w3 = wkb[m + 3];
                            float x0 = mkb[(m) * KD + d0],     y0 = mkb[(m) * KD + d0 + 1];
                            float x1 = mkb[(m + 1) * KD + d0], y1 = mkb[(m + 1) * KD + d0 + 1];
                            float x2 = mkb[(m + 2) * KD + d0], y2 = mkb[(m + 2) * KD + d0 + 1];
                            float x3 = mkb[(m + 3) * KD + d0], y3 = mkb[(m + 3) * KD + d0 + 1];
                            v0 += w0 * x0 + w1 * x1 + w2 * x2 + w3 * x3;
                            v1 += w0 * y0 + w1 * y1 + w2 * y2 + w3 * y3;
                        }
                        for (; m < t; m++) {
                            float w = wkb[m];
                            v0 += w * mkb[m * KD + d0];
                            v1 += w * mkb[m * KD + d0 + 1];
                        }
                    } else {
                        for (int m = 0; m < t; m++) v0 += wkb[m] * ckb[m];
                    }
                    v0 *= gv; v1 *= gv;
                    __nv_bfloat16 h0 = __float2bfloat16_rn(v0);
                    __nv_bfloat16 h1 = __float2bfloat16_rn(v1);
                    int ch = d0 >> 4, kk = d0 & 15;
                    int lane_a = (r & 7) * 4 + ((kk & 7) >> 1);
                    int w = (r >> 3) + ((kk >> 3) << 1);
                    size_t widx = ((size_t)(m16 * NCHP + ch)) * 128 + lane_a * 4 + w;
                    oH[widx] = (unsigned)__bfloat16_as_ushort(h1) << 16 |
                               __bfloat16_as_ushort(h0);
                    oL[widx] = packbf2(v0 - __bfloat162float(h0),
                                       v1 - __bfloat162float(h1));
                }
            }
            // producer arrival: key_r (and Mk) for step t complete on this block
            __syncthreads();
            if (tid == 0) { __threadfence(); atomicAdd(&g_kr, 1u); }
        } else {  // t == 32: y_lin + argmax
            if (bx >= 64 && bx < 128 && wid < 8) {
                int bb = (bx - 64) * 8 + wid;
                const float* hb = d_h + (size_t)bb * HD;
                float yv[4];
#pragma unroll
                for (int yi = 0; yi < YD; yi++) {
                    float s = 0.f;
                    for (int l = lane; l < HD; l += 32) s += hb[l] * W_y[yi * HD + l];
#pragma unroll
                    for (int o = 16; o; o >>= 1) s += __shfl_xor_sync(0xffffffffu, s, o);
                    yv[yi] = s + b_y[yi];
                }
                if (lane == 0) {
                    int am = 0; float bst = yv[0];
#pragma unroll
                    for (int yi = 1; yi < YD; yi++)
                        if (yv[yi] > bst) { bst = yv[yi]; am = yi; }
                    if (out_size >= BD * YD) {
                        float* of = (float*)outp;
                        of[bb * 4 + 0] = yv[0];
                        of[bb * 4 + 1] = yv[1];
                        of[bb * 4 + 2] = yv[2];
                        of[bb * 4 + 3] = yv[3];
                        if (out_size >= BD * YD + BD) of[BD * YD + bb] = (float)am;
                    } else {
                        ((int*)outp)[bb] = am;
                    }
                }
            }
        }
    }
}

// ------------------------------- launcher ----------------------------------
extern "C" void kernel_launch(void* const* d_in, const int* in_sizes, int n_in,
                              void* d_out, int out_size)
{
    const float* x_seq  = (const float*)d_in[0];
    const float* W_enc  = (const float*)d_in[1];
    const float* gamma  = (const float*)d_in[2];
    const float* beta   = (const float*)d_in[3];
    const float* W_ih   = (const float*)d_in[4];
    const float* W_hh   = (const float*)d_in[5];
    const float* b_ih   = (const float*)d_in[6];
    const float* b_hh   = (const float*)d_in[7];
    const float* W_key  = (const float*)d_in[8];
    const float* b_key  = (const float*)d_in[9];
    const float* W_g    = (const float*)d_in[10];
    const float* b_g    = (const float*)d_in[11];
    const float* cgain  = (const float*)d_in[12];
    const float* cbias  = (const float*)d_in[13];
    const float* W_y    = (const float*)d_in[14];
    const float* b_y    = (const float*)d_in[15];

    cudaFuncSetAttribute(recur, cudaFuncAttributeMaxDynamicSharedMemorySize,
                         SMEM_RECUR);

    prep_kernel<<<1024, 256>>>(W_ih, W_hh, b_ih, b_hh, W_key, W_enc);
    enc_gemm2<<<128, 256>>>(x_seq);
    norm_attn<<<BD, 256>>>(gamma, beta, cgain, cbias);
    recur<<<NB, NT, SMEM_RECUR>>>(b_key, W_g, b_g, W_y, b_y, d_out, out_size);
}